// round 16
// baseline (speedup 1.0000x reference)
#include <cuda_runtime.h>
#include <cuda_bf16.h>
#include <cstdint>

// Problem dims
#define BATCH 8
#define MODEL_DIM 1024
#define HIGH_DIM 2048
#define TDIM 4096
#define KEEP 64

// Arbitration band half-width (covers bf16-split GEMM error, sigma ~6e-6)
#define TAU 1.5e-4f
#define CAND_CAP 128
// per-(b,t) column bucket capacity (mean 32 nonzeros, Poisson tail << 192)
#define COLCAP 192

// ---------------- scratch (static device globals; no allocations) -------------
__device__ float g_y[(size_t)BATCH * HIGH_DIM * TDIM];     // 256 MB intermediate y
__device__ float g_WcT[(size_t)HIGH_DIM * MODEL_DIM];      // 8 MB transposed W_c
__device__ __nv_bfloat16 g_WeH[(size_t)HIGH_DIM * MODEL_DIM];
__device__ __nv_bfloat16 g_WeL[(size_t)HIGH_DIM * MODEL_DIM];
__device__ __nv_bfloat16 g_xTH[(size_t)BATCH * TDIM * MODEL_DIM];  // x^T hi [b][t][c]
__device__ __nv_bfloat16 g_xTL[(size_t)BATCH * TDIM * MODEL_DIM];  // x^T lo
__device__ int   g_colcnt[BATCH * TDIM];
__device__ short g_cold[(size_t)BATCH * TDIM * COLCAP];
__device__ float g_colv[(size_t)BATCH * TDIM * COLCAP];

// ======================= PTX helpers (base sm_103 ISA only) ==================
__device__ __forceinline__ uint32_t smem_to_u32(const void* p) {
    uint32_t a;
    asm("{ .reg .u64 t; cvta.to.shared.u64 t, %1; cvt.u32.u64 %0, t; }" : "=r"(a) : "l"(p));
    return a;
}
#define SWZ128(off) ((off) ^ (((off) >> 3) & 0x70))

__device__ __forceinline__ void cp_async16(uint32_t dst, const void* src) {
    asm volatile("cp.async.cg.shared.global [%0], [%1], 16;" :: "r"(dst), "l"(src));
}
#define CP_COMMIT() asm volatile("cp.async.commit_group;" ::: "memory")
#define CP_WAIT(n)  asm volatile("cp.async.wait_group %0;" :: "n"(n) : "memory")

#define LDSM_X4(r0, r1, r2, r3, addr) \
    asm volatile("ldmatrix.sync.aligned.m8n8.x4.shared.b16 {%0,%1,%2,%3}, [%4];" \
                 : "=r"(r0), "=r"(r1), "=r"(r2), "=r"(r3) : "r"(addr))

#define MMA16816(d, a, b) \
    asm volatile("mma.sync.aligned.m16n8k16.row.col.f32.bf16.bf16.f32 " \
                 "{%0,%1,%2,%3}, {%4,%5,%6,%7}, {%8,%9}, {%0,%1,%2,%3};" \
                 : "+f"((d)[0]), "+f"((d)[1]), "+f"((d)[2]), "+f"((d)[3]) \
                 : "r"((a)[0]), "r"((a)[1]), "r"((a)[2]), "r"((a)[3]), \
                   "r"((b)[0]), "r"((b)[1]))

// =============================================================================
// Prep kernels: bf16 hi/lo splits (We elementwise; x transposed to [b][t][c])
// =============================================================================
__global__ __launch_bounds__(256) void split_we_kernel(const float* __restrict__ We)
{
    const int i = blockIdx.x * 256 + threadIdx.x;   // grid covers 2M elems
    float v = We[i];
    __nv_bfloat16 h = __float2bfloat16(v);
    g_WeH[i] = h;
    g_WeL[i] = __float2bfloat16(v - __bfloat162float(h));
    if (i < BATCH * TDIM) g_colcnt[i] = 0;          // fused bucket reset
}

__global__ void split_x_kernel(const float* __restrict__ x)
{
    __shared__ float tile[32][33];
    const int b = blockIdx.z;
    const int t0 = blockIdx.x * 32;
    const int c0 = blockIdx.y * 32;
    const int tx = threadIdx.x, ty = threadIdx.y;   // 32 x 8
    const float* xb = x + (size_t)b * MODEL_DIM * TDIM;
    for (int i = ty; i < 32; i += 8)
        tile[i][tx] = xb[(size_t)(c0 + i) * TDIM + t0 + tx];
    __syncthreads();
    for (int i = ty; i < 32; i += 8) {
        float v = tile[tx][i];                       // c = c0+tx, t = t0+i
        __nv_bfloat16 h = __float2bfloat16(v);
        size_t o = ((size_t)b * TDIM + t0 + i) * MODEL_DIM + c0 + tx;
        g_xTH[o] = h;
        g_xTL[o] = __float2bfloat16(v - __bfloat162float(h));
    }
}

// =============================================================================
// Kernel 1: HMMA bf16 hi/lo split expand GEMM — CTA tile 128(M) x 256(N),
// 256 threads (8 warps, each 64x64). 4-STAGE ring at BK=32 (48KB/stage,
// 192KB total): steady-state waits only on a stage loaded TWO chunks ago
// (CP_WAIT(2)), hiding the per-chunk load tail that capped tensor at 77%.
// k16-step order unchanged (64 ascending steps, HH->HL->LH) -> bit-identical y.
// =============================================================================
#define GKB 32                                      // BK
#define GA_BYTES (128 * GKB * 2)                    // 8 KB per A tile
#define GB_BYTES (256 * GKB * 2)                    // 16 KB per B tile
#define GSTAGE_BYTES (2 * GA_BYTES + 2 * GB_BYTES)  // 48 KB
#define GSMEM_TOTAL (4 * GSTAGE_BYTES)              // 192 KB, 4-stage ring
#define NCHUNK 32                                   // 1024 / 32
#define KROW_B 64                                   // smem row = 64 bytes (32 bf16)

// SW64-style swizzle for 64-byte rows: XOR bits[5:4] with bits[8:7]
#define SWZ64(off) ((off) ^ (((off) >> 3) & 0x30))

__global__ __launch_bounds__(256, 1) void gemm_expand_mma(const float* __restrict__ be)
{
    extern __shared__ char sm[];
    const uint32_t smem_base = smem_to_u32(sm);
    const int tid = threadIdx.x;
    const int w = tid >> 5;                       // 0..7
    const int lane = tid & 31;

    const int b = blockIdx.z;
    const int tileM = blockIdx.y * 128;           // d
    const int tileN = blockIdx.x * 256;           // t

    const int m0 = (w & 1) * 64;                  // warp M offset (4 m16 tiles)
    const int n0 = (w >> 1) * 64;                 // warp N offset (8 n8 tiles)

    float acc[4][8][4];
#pragma unroll
    for (int mt = 0; mt < 4; mt++)
#pragma unroll
        for (int nt = 0; nt < 8; nt++)
#pragma unroll
            for (int r = 0; r < 4; r++) acc[mt][nt][r] = 0.f;

    const size_t aRowBase = (size_t)tileM * MODEL_DIM;
    const size_t bRowBase = ((size_t)b * TDIM + tileN) * MODEL_DIM;

    // stage layout: [AH 8K][AL 8K][BH 16K][BL 16K], rows of 64 bytes, SWZ64
    auto load_stage = [&](int kc, int buf) {
        const int k0 = kc * GKB;
        const uint32_t base = smem_base + (uint32_t)buf * GSTAGE_BYTES;
        // 3072 16B-chunks total: A tiles 2*512, B tiles 2*1024
#pragma unroll
        for (int i = 0; i < 12; i++) {
            const int cid = i * 256 + tid;         // 0..3071
            if (cid < 1024) {                      // A tiles: AH then AL
                const int tile = cid >> 9;         // 0=AH, 1=AL
                const int idx = cid & 511;
                const int row = idx >> 2;          // 0..127
                const int c16 = idx & 3;           // 16B chunk within 64B row
                const uint32_t dst = base + (uint32_t)tile * GA_BYTES
                                     + SWZ64((uint32_t)(row * KROW_B + c16 * 16));
                const size_t off = (size_t)row * MODEL_DIM + k0 + c16 * 8;
                cp_async16(dst, (tile ? g_WeL : g_WeH) + aRowBase + off);
            } else {                               // B tiles: BH then BL
                const int t2 = cid - 1024;
                const int tile = t2 >> 10;         // 0=BH, 1=BL
                const int idx = t2 & 1023;
                const int row = idx >> 2;          // 0..255
                const int c16 = idx & 3;
                const uint32_t dst = base + 2 * GA_BYTES + (uint32_t)tile * GB_BYTES
                                     + SWZ64((uint32_t)(row * KROW_B + c16 * 16));
                const size_t off = (size_t)row * MODEL_DIM + k0 + c16 * 8;
                cp_async16(dst, (tile ? g_xTL : g_xTH) + bRowBase + off);
            }
        }
        CP_COMMIT();
    };

    // prologue: 3 stages in flight
    load_stage(0, 0);
    load_stage(1, 1);
    load_stage(2, 2);

    for (int it = 0; it < NCHUNK; it++) {
        CP_WAIT(2);               // stage `it` complete (loaded >=2 chunks ago)
        __syncthreads();          // all warps done computing stage it-1
        if (it + 3 < NCHUNK) load_stage(it + 3, (it + 3) & 3);
        else CP_COMMIT();         // empty group keeps wait-depth math constant

        const uint32_t base = smem_base + (uint32_t)(it & 3) * GSTAGE_BYTES;
        const uint32_t AH = base;
        const uint32_t AL = base + GA_BYTES;
        const uint32_t BH = base + 2 * GA_BYTES;
        const uint32_t BL = base + 2 * GA_BYTES + GB_BYTES;

#pragma unroll 1
        for (int ks = 0; ks < 2; ks++) {
            uint32_t afH[4][4], afL[4][4];
#pragma unroll
            for (int mt = 0; mt < 4; mt++) {
                const int row = m0 + mt * 16 + ((lane >> 3) & 1) * 8 + (lane & 7);
                const int c16 = ks * 2 + (lane >> 4);
                const uint32_t so = SWZ64((uint32_t)(row * KROW_B + c16 * 16));
                LDSM_X4(afH[mt][0], afH[mt][1], afH[mt][2], afH[mt][3], AH + so);
                LDSM_X4(afL[mt][0], afL[mt][1], afL[mt][2], afL[mt][3], AL + so);
            }
            uint32_t bfH[8][2], bfL[8][2];
#pragma unroll
            for (int j = 0; j < 4; j++) {
                const int row = n0 + j * 16 + (lane >> 4) * 8 + (lane & 7);
                const int c16 = ks * 2 + ((lane >> 3) & 1);
                const uint32_t so = SWZ64((uint32_t)(row * KROW_B + c16 * 16));
                LDSM_X4(bfH[2 * j][0], bfH[2 * j][1],
                        bfH[2 * j + 1][0], bfH[2 * j + 1][1], BH + so);
                LDSM_X4(bfL[2 * j][0], bfL[2 * j][1],
                        bfL[2 * j + 1][0], bfL[2 * j + 1][1], BL + so);
            }
#pragma unroll
            for (int mt = 0; mt < 4; mt++)
#pragma unroll
                for (int nt = 0; nt < 8; nt++) {
                    MMA16816(acc[mt][nt], afH[mt], bfH[nt]);   // H*H
                    MMA16816(acc[mt][nt], afH[mt], bfL[nt]);   // H*L
                    MMA16816(acc[mt][nt], afL[mt], bfH[nt]);   // L*H
                }
        }
    }

    // Epilogue: thread (g=lane>>2, ti=lane&3) holds (g,2ti),(g,2ti+1),(g+8,..)
    const int g = lane >> 2;
    const int ti = lane & 3;
#pragma unroll
    for (int mt = 0; mt < 4; mt++) {
        const int d0 = tileM + m0 + mt * 16 + g;
        const int d1 = d0 + 8;
        const float bias0 = __ldg(&be[d0]);
        const float bias1 = __ldg(&be[d1]);
        float* y0 = g_y + ((size_t)b * HIGH_DIM + d0) * TDIM + tileN + n0;
        float* y1 = g_y + ((size_t)b * HIGH_DIM + d1) * TDIM + tileN + n0;
#pragma unroll
        for (int nt = 0; nt < 8; nt++) {
            const int col = nt * 8 + 2 * ti;
            float2 v0 = make_float2(acc[mt][nt][0] + bias0, acc[mt][nt][1] + bias0);
            float2 v1 = make_float2(acc[mt][nt][2] + bias1, acc[mt][nt][3] + bias1);
            *reinterpret_cast<float2*>(y0 + col) = v0;
            *reinterpret_cast<float2*>(y1 + col) = v1;
        }
    }
}

// =============================================================================
// Kernel 2: per-row (b,d) top-64 with fp64 boundary arbitration.
// (R15-measured-best: smem uint4 keys, shared 256-bin hist, warp-parallel
// suffix-scan bin selection.)
// =============================================================================
__device__ __forceinline__ unsigned f2key(unsigned bits) {
    return bits ^ (((unsigned)((int)bits >> 31)) | 0x80000000u);
}
__device__ __forceinline__ float key2f(unsigned k) {
    unsigned bits = (k & 0x80000000u) ? (k ^ 0x80000000u) : ~k;
    return __uint_as_float(bits);
}

__global__ __launch_bounds__(256) void topk_kernel(
    const float* __restrict__ x,
    const float* __restrict__ We,
    const float* __restrict__ be,
    float* __restrict__ sparse_out)
{
    const int row = blockIdx.x;          // b*HIGH_DIM + d
    const int b = row / HIGH_DIM;
    const int d = row % HIGH_DIM;
    const size_t rowoff = (size_t)row * TDIM;

    __shared__ unsigned keys[TDIM];      // 16 KB
    __shared__ int hist[256];
    __shared__ unsigned s_prefix, s_mask;
    __shared__ int s_need;
    __shared__ int s_above, s_ncand;
    __shared__ int s_cidx[CAND_CAP];
    __shared__ double s_cex[CAND_CAP];
    __shared__ unsigned char s_take[CAND_CAP];

    const int tid = threadIdx.x;
    const int lane = tid & 31;
    const int w = tid >> 5;

    // vectorized key load
    {
        const uint4* yrow4 = reinterpret_cast<const uint4*>(g_y + rowoff);
        uint4* keys4 = reinterpret_cast<uint4*>(keys);
#pragma unroll
        for (int i = tid; i < TDIM / 4; i += 256) {
            uint4 v = yrow4[i];
            v.x = f2key(v.x); v.y = f2key(v.y); v.z = f2key(v.z); v.w = f2key(v.w);
            keys4[i] = v;
        }
    }
    if (tid == 0) { s_prefix = 0u; s_mask = 0u; s_need = KEEP; s_above = 0; s_ncand = 0; }
    __syncthreads();

    for (int pass = 0; pass < 4; pass++) {
        const int shift = 24 - pass * 8;
        hist[tid] = 0;
        __syncthreads();
        const unsigned pf = s_prefix, mk = s_mask;
        const uint4* keys4 = reinterpret_cast<const uint4*>(keys);
#pragma unroll
        for (int i = tid; i < TDIM / 4; i += 256) {
            uint4 k = keys4[i];
            if ((k.x & mk) == pf) atomicAdd(&hist[(k.x >> shift) & 0xFF], 1);
            if ((k.y & mk) == pf) atomicAdd(&hist[(k.y >> shift) & 0xFF], 1);
            if ((k.z & mk) == pf) atomicAdd(&hist[(k.z >> shift) & 0xFF], 1);
            if ((k.w & mk) == pf) atomicAdd(&hist[(k.w >> shift) & 0xFF], 1);
        }
        __syncthreads();
        // warp-parallel bin selection (warp 0): lane owns bins [8l, 8l+7]
        if (w == 0) {
            const int need = s_need;
            int h[8];
            int local = 0;
#pragma unroll
            for (int i = 0; i < 8; i++) { h[i] = hist[lane * 8 + i]; local += h[i]; }
            // suffix sum across lanes: T[l] = sum of bins 8l..255
            int T = local;
#pragma unroll
            for (int o = 1; o < 32; o <<= 1) {
                int v = __shfl_down_sync(0xFFFFFFFFu, T, o);
                if (lane + o < 32) T += v;
            }
            int tnext = __shfl_down_sync(0xFFFFFFFFu, T, 1);
            if (lane == 31) tnext = 0;
            // exactly one lane has the crossing: T >= need > tnext
            if (T >= need && tnext < need) {
                int cum = tnext;                  // sum of bins > 8*lane+7
                int bin = 0;
#pragma unroll
                for (int i = 7; i >= 0; i--) {
                    if (cum + h[i] >= need) { bin = lane * 8 + i; break; }
                    cum += h[i];
                }
                s_need = need - cum;
                s_prefix = pf | ((unsigned)bin << shift);
                s_mask = mk | (0xFFu << shift);
            }
        }
        __syncthreads();
    }

    const float v64 = key2f(s_prefix);
    const float hi = v64 + TAU;
    const float lo = v64 - TAU;
    const unsigned khi = f2key(__float_as_uint(hi));
    const unsigned klo = f2key(__float_as_uint(lo));

    // classify on keys directly (order-preserving): k > khi above; k >= klo in band
    {
        const uint4* keys4 = reinterpret_cast<const uint4*>(keys);
#pragma unroll
        for (int i = tid; i < TDIM / 4; i += 256) {
            uint4 k = keys4[i];
            int above = (k.x > khi) + (k.y > khi) + (k.z > khi) + (k.w > khi);
            if (above) atomicAdd(&s_above, above);
#pragma unroll
            for (int e = 0; e < 4; e++) {
                unsigned ke = (e == 0) ? k.x : (e == 1) ? k.y : (e == 2) ? k.z : k.w;
                if (ke <= khi && ke >= klo) {
                    int p = atomicAdd(&s_ncand, 1);
                    if (p < CAND_CAP) s_cidx[p] = i * 4 + e;
                }
            }
        }
    }
    __syncthreads();

    const int slots = KEEP - s_above;
    const int nc = min(s_ncand, CAND_CAP);
    const bool simple = (s_ncand == slots);

    if (!simple) {
        const float* wr = We + (size_t)d * MODEL_DIM;
        const float* xb = x + (size_t)b * MODEL_DIM * TDIM;
        for (int p = w; p < nc; p += 8) {
            const int t = s_cidx[p];
            double s = 0.0;
            for (int c = lane; c < MODEL_DIM; c += 32)
                s += (double)wr[c] * (double)xb[(size_t)c * TDIM + t];
#pragma unroll
            for (int o = 16; o > 0; o >>= 1)
                s += __shfl_down_sync(0xFFFFFFFFu, s, o);
            if (lane == 0) s_cex[p] = s + (double)be[d];
        }
        __syncthreads();
        for (int p = tid; p < nc; p += 256) {
            const float ef = (float)s_cex[p];
            const int gi = s_cidx[p];
            int better = 0;
            for (int q = 0; q < nc; q++) {
                if (q == p) continue;
                const float qf = (float)s_cex[q];
                if (qf > ef || (qf == ef && s_cidx[q] < gi)) better++;
            }
            s_take[p] = (better < slots) ? 1 : 0;
        }
        __syncthreads();
    }

    // vectorized writeback + bucket append
    {
        float4* sp4 = reinterpret_cast<float4*>(sparse_out + rowoff);
        const uint4* keys4 = reinterpret_cast<const uint4*>(keys);
#pragma unroll
        for (int i = tid; i < TDIM / 4; i += 256) {
            uint4 k = keys4[i];
            float4 outv;
#pragma unroll
            for (int e = 0; e < 4; e++) {
                unsigned ke = (e == 0) ? k.x : (e == 1) ? k.y : (e == 2) ? k.z : k.w;
                bool take;
                if (ke > khi) take = true;
                else if (ke < klo) take = false;
                else if (simple) take = true;
                else {
                    take = false;
                    const int gi = i * 4 + e;
                    for (int p = 0; p < nc; p++)
                        if (s_cidx[p] == gi) { take = (s_take[p] != 0); break; }
                }
                float yv = take ? key2f(ke) : 0.f;
                if (e == 0) outv.x = yv; else if (e == 1) outv.y = yv;
                else if (e == 2) outv.z = yv; else outv.w = yv;
                if (take) {
                    const int col = b * TDIM + i * 4 + e;
                    int pos = atomicAdd(&g_colcnt[col], 1);
                    if (pos < COLCAP) {
                        g_cold[(size_t)col * COLCAP + pos] = (short)d;
                        g_colv[(size_t)col * COLCAP + pos] = key2f(ke);
                    }
                }
            }
            sp4[i] = outv;
        }
    }
}

// =============================================================================
// Kernel 3: transpose W_c [1024 x 2048] -> W_cT [2048 x 1024]
// =============================================================================
__global__ void transpose_wc_kernel(const float* __restrict__ Wc)
{
    __shared__ float tile[32][33];
    const int d0 = blockIdx.x * 32;
    const int m0 = blockIdx.y * 32;
    const int tx = threadIdx.x, ty = threadIdx.y;
    for (int i = ty; i < 32; i += 8)
        tile[i][tx] = Wc[(size_t)(m0 + i) * HIGH_DIM + d0 + tx];
    __syncthreads();
    for (int i = ty; i < 32; i += 8)
        g_WcT[(size_t)(d0 + i) * MODEL_DIM + m0 + tx] = tile[tx][i];
}

// =============================================================================
// Kernel 4: sparse contract from compact per-column lists, coalesced epilogue.
// (Measured near its ~4GB L2-read floor; unchanged.)
// =============================================================================
#define TTILE 8

__global__ __launch_bounds__(256) void contract_kernel(
    const float* __restrict__ bc,
    float* __restrict__ out)
{
    const int b = blockIdx.y;
    const int t0 = blockIdx.x * TTILE;

    __shared__ short sd[TTILE][COLCAP];
    __shared__ float sv[TTILE][COLCAP];
    __shared__ int scnt[TTILE];
    __shared__ float sm_out[TTILE][MODEL_DIM];   // 32 KB

    const int tid = threadIdx.x;
    const int lane = tid & 31;
    const int w = tid >> 5;             // 8 warps = 8 columns

    // load this warp's column list
    {
        const int col = b * TDIM + t0 + w;
        const int n = min(g_colcnt[col], COLCAP);
        if (lane == 0) scnt[w] = n;
        const size_t base = (size_t)col * COLCAP;
        for (int j = lane; j < n; j += 32) {
            sd[w][j] = g_cold[base + j];
            sv[w][j] = g_colv[base + j];
        }
    }
    __syncwarp();

    // sort by d ascending (deterministic order); n ~ 32, lane 0 insertion sort
    if (lane == 0) {
        const int n = scnt[w];
        for (int i = 1; i < n; i++) {
            short dk = sd[w][i]; float vk = sv[w][i];
            int j = i - 1;
            while (j >= 0 && sd[w][j] > dk) {
                sd[w][j + 1] = sd[w][j]; sv[w][j + 1] = sv[w][j]; j--;
            }
            sd[w][j + 1] = dk; sv[w][j + 1] = vk;
        }
    }
    __syncwarp();

    // accumulate: lane covers m = i*128 + lane*4 .. +3
    {
        const int n = scnt[w];
        float4 a4[8];
#pragma unroll
        for (int i = 0; i < 8; i++) a4[i] = make_float4(0.f, 0.f, 0.f, 0.f);
        for (int j = 0; j < n; j++) {
            const float val = sv[w][j];
            const float4* wr4 = reinterpret_cast<const float4*>(
                g_WcT + (size_t)sd[w][j] * MODEL_DIM);
#pragma unroll
            for (int i = 0; i < 8; i++) {
                float4 v = wr4[i * 32 + lane];
                a4[i].x = fmaf(val, v.x, a4[i].x);
                a4[i].y = fmaf(val, v.y, a4[i].y);
                a4[i].z = fmaf(val, v.z, a4[i].z);
                a4[i].w = fmaf(val, v.w, a4[i].w);
            }
        }
#pragma unroll
        for (int i = 0; i < 8; i++)
            *reinterpret_cast<float4*>(&sm_out[w][i * 128 + lane * 4]) = a4[i];
    }
    __syncthreads();

    // coalesced writeback: thread handles rows m = tid + 256*r
    float* ob = out + (size_t)b * MODEL_DIM * TDIM + t0;
#pragma unroll
    for (int r = 0; r < 4; r++) {
        const int m = tid + 256 * r;
        const float bias = bc[m];
        float4 v0, v1;
        v0.x = sm_out[0][m] + bias; v0.y = sm_out[1][m] + bias;
        v0.z = sm_out[2][m] + bias; v0.w = sm_out[3][m] + bias;
        v1.x = sm_out[4][m] + bias; v1.y = sm_out[5][m] + bias;
        v1.z = sm_out[6][m] + bias; v1.w = sm_out[7][m] + bias;
        float* op = ob + (size_t)m * TDIM;
        *reinterpret_cast<float4*>(op) = v0;
        *reinterpret_cast<float4*>(op + 4) = v1;
    }
}

// =============================================================================
// launch
// =============================================================================
extern "C" void kernel_launch(void* const* d_in, const int* in_sizes, int n_in,
                              void* d_out, int out_size)
{
    const float* x  = (const float*)d_in[0];   // [8,1024,4096]
    const float* We = (const float*)d_in[1];   // [2048,1024]
    const float* be = (const float*)d_in[2];   // [2048]
    const float* Wc = (const float*)d_in[3];   // [1024,2048]
    const float* bc = (const float*)d_in[4];   // [1024]

    float* out_ptr = (float*)d_out;                                       // [8,1024,4096]
    float* sparse_ptr = (float*)d_out + (size_t)BATCH * MODEL_DIM * TDIM; // [8,2048,4096]

    cudaFuncSetAttribute(gemm_expand_mma,
                         cudaFuncAttributeMaxDynamicSharedMemorySize, GSMEM_TOTAL);

    // prep: bf16 splits (+fused bucket reset) + W_c transpose
    split_we_kernel<<<(HIGH_DIM * MODEL_DIM) / 256, 256>>>(We);
    split_x_kernel<<<dim3(TDIM / 32, MODEL_DIM / 32, BATCH), dim3(32, 8)>>>(x);
    transpose_wc_kernel<<<dim3(HIGH_DIM / 32, MODEL_DIM / 32), dim3(32, 8)>>>(Wc);

    // expand GEMM on tensor cores (HMMA, 128x256 tile, 4-stage BK=32 pipeline)
    gemm_expand_mma<<<dim3(TDIM / 256, HIGH_DIM / 128, BATCH), 256, GSMEM_TOTAL>>>(be);

    // top-k (writes sparse region + column buckets)
    topk_kernel<<<BATCH * HIGH_DIM, 256>>>(x, We, be, sparse_ptr);

    // contract from compact lists
    contract_kernel<<<dim3(TDIM / TTILE, BATCH), 256>>>(bc, out_ptr);
}

// round 17
// speedup vs baseline: 1.0795x; 1.0795x over previous
#include <cuda_runtime.h>
#include <cuda_bf16.h>
#include <cstdint>

// Problem dims
#define BATCH 8
#define MODEL_DIM 1024
#define HIGH_DIM 2048
#define TDIM 4096
#define KEEP 64

// Arbitration band half-width (covers bf16-split GEMM error, sigma ~6e-6)
#define TAU 1.5e-4f
#define CAND_CAP 128
// per-(b,t) column bucket capacity (mean 32 nonzeros, Poisson tail << 192)
#define COLCAP 192

// ---------------- scratch (static device globals; no allocations) -------------
__device__ float g_y[(size_t)BATCH * HIGH_DIM * TDIM];     // 256 MB intermediate y
__device__ float g_WcT[(size_t)HIGH_DIM * MODEL_DIM];      // 8 MB transposed W_c
__device__ __nv_bfloat16 g_WeH[(size_t)HIGH_DIM * MODEL_DIM];
__device__ __nv_bfloat16 g_WeL[(size_t)HIGH_DIM * MODEL_DIM];
__device__ __nv_bfloat16 g_xTH[(size_t)BATCH * TDIM * MODEL_DIM];  // x^T hi [b][t][c]
__device__ __nv_bfloat16 g_xTL[(size_t)BATCH * TDIM * MODEL_DIM];  // x^T lo
__device__ int   g_colcnt[BATCH * TDIM];
__device__ short g_cold[(size_t)BATCH * TDIM * COLCAP];
__device__ float g_colv[(size_t)BATCH * TDIM * COLCAP];

// ======================= PTX helpers (base sm_103 ISA only) ==================
__device__ __forceinline__ uint32_t smem_to_u32(const void* p) {
    uint32_t a;
    asm("{ .reg .u64 t; cvta.to.shared.u64 t, %1; cvt.u32.u64 %0, t; }" : "=r"(a) : "l"(p));
    return a;
}
#define SWZ128(off) ((off) ^ (((off) >> 3) & 0x70))

__device__ __forceinline__ void cp_async16(uint32_t dst, const void* src) {
    asm volatile("cp.async.cg.shared.global [%0], [%1], 16;" :: "r"(dst), "l"(src));
}
#define CP_COMMIT() asm volatile("cp.async.commit_group;" ::: "memory")
#define CP_WAIT(n)  asm volatile("cp.async.wait_group %0;" :: "n"(n) : "memory")

#define LDSM_X4(r0, r1, r2, r3, addr) \
    asm volatile("ldmatrix.sync.aligned.m8n8.x4.shared.b16 {%0,%1,%2,%3}, [%4];" \
                 : "=r"(r0), "=r"(r1), "=r"(r2), "=r"(r3) : "r"(addr))

#define MMA16816(d, a, b) \
    asm volatile("mma.sync.aligned.m16n8k16.row.col.f32.bf16.bf16.f32 " \
                 "{%0,%1,%2,%3}, {%4,%5,%6,%7}, {%8,%9}, {%0,%1,%2,%3};" \
                 : "+f"((d)[0]), "+f"((d)[1]), "+f"((d)[2]), "+f"((d)[3]) \
                 : "r"((a)[0]), "r"((a)[1]), "r"((a)[2]), "r"((a)[3]), \
                   "r"((b)[0]), "r"((b)[1]))

// =============================================================================
// Prep kernels: bf16 hi/lo splits (We elementwise; x transposed to [b][t][c])
// =============================================================================
__global__ __launch_bounds__(256) void split_we_kernel(const float* __restrict__ We)
{
    const int i = blockIdx.x * 256 + threadIdx.x;   // grid covers 2M elems
    float v = We[i];
    __nv_bfloat16 h = __float2bfloat16(v);
    g_WeH[i] = h;
    g_WeL[i] = __float2bfloat16(v - __bfloat162float(h));
    if (i < BATCH * TDIM) g_colcnt[i] = 0;          // fused bucket reset
}

__global__ void split_x_kernel(const float* __restrict__ x)
{
    __shared__ float tile[32][33];
    const int b = blockIdx.z;
    const int t0 = blockIdx.x * 32;
    const int c0 = blockIdx.y * 32;
    const int tx = threadIdx.x, ty = threadIdx.y;   // 32 x 8
    const float* xb = x + (size_t)b * MODEL_DIM * TDIM;
    for (int i = ty; i < 32; i += 8)
        tile[i][tx] = xb[(size_t)(c0 + i) * TDIM + t0 + tx];
    __syncthreads();
    for (int i = ty; i < 32; i += 8) {
        float v = tile[tx][i];                       // c = c0+tx, t = t0+i
        __nv_bfloat16 h = __float2bfloat16(v);
        size_t o = ((size_t)b * TDIM + t0 + i) * MODEL_DIM + c0 + tx;
        g_xTH[o] = h;
        g_xTL[o] = __float2bfloat16(v - __bfloat162float(h));
    }
}

// =============================================================================
// Kernel 1: HMMA bf16 hi/lo split expand GEMM — CTA tile 128(M) x 256(N),
// 256 threads (8 warps, each 64x64), BK=64, double-buffered 96KB stages.
// (R15 configuration: measured 883us / tensor 77% — the optimum of this
// family; BK=32 deeper pipelining measured WORSE at 983us / 69%.)
// =============================================================================
#define GA_BYTES 16384                              // 128x64 bf16
#define GB_BYTES 32768                              // 256x64 bf16
#define GSTAGE_BYTES (2 * GA_BYTES + 2 * GB_BYTES)  // 96 KB
#define GSMEM_TOTAL (2 * GSTAGE_BYTES)              // 192 KB double buffer
#define NCHUNK 16                                   // 1024 / 64

__global__ __launch_bounds__(256, 1) void gemm_expand_mma(const float* __restrict__ be)
{
    extern __shared__ char sm[];
    const uint32_t smem_base = smem_to_u32(sm);
    const int tid = threadIdx.x;
    const int w = tid >> 5;                       // 0..7
    const int lane = tid & 31;

    const int b = blockIdx.z;
    const int tileM = blockIdx.y * 128;           // d
    const int tileN = blockIdx.x * 256;           // t

    const int m0 = (w & 1) * 64;                  // warp M offset (4 m16 tiles)
    const int n0 = (w >> 1) * 64;                 // warp N offset (8 n8 tiles)

    float acc[4][8][4];
#pragma unroll
    for (int mt = 0; mt < 4; mt++)
#pragma unroll
        for (int nt = 0; nt < 8; nt++)
#pragma unroll
            for (int r = 0; r < 4; r++) acc[mt][nt][r] = 0.f;

    const size_t aRowBase = (size_t)tileM * MODEL_DIM;
    const size_t bRowBase = ((size_t)b * TDIM + tileN) * MODEL_DIM;

    auto load_stage = [&](int kc, int buf) {
        const int k0 = kc * 64;
        const uint32_t base = smem_base + (uint32_t)buf * GSTAGE_BYTES;
#pragma unroll
        for (int i = 0; i < 24; i++) {
            const int cid = i * 256 + tid;         // 0..6143
            if (cid < 2048) {                      // A tiles: AH then AL
                const int tile = cid >> 10;        // 0=AH, 1=AL
                const int idx = cid & 1023;
                const int row = idx >> 3;          // 0..127
                const int c16 = idx & 7;
                const uint32_t dst = base + (uint32_t)tile * GA_BYTES
                                     + SWZ128((uint32_t)(row * 128 + c16 * 16));
                const size_t off = (size_t)row * MODEL_DIM + k0 + c16 * 8;
                cp_async16(dst, (tile ? g_WeL : g_WeH) + aRowBase + off);
            } else {                               // B tiles: BH then BL
                const int t2 = cid - 2048;
                const int tile = t2 >> 11;         // 0=BH, 1=BL
                const int idx = t2 & 2047;
                const int row = idx >> 3;          // 0..255
                const int c16 = idx & 7;
                const uint32_t dst = base + 2 * GA_BYTES + (uint32_t)tile * GB_BYTES
                                     + SWZ128((uint32_t)(row * 128 + c16 * 16));
                const size_t off = (size_t)row * MODEL_DIM + k0 + c16 * 8;
                cp_async16(dst, (tile ? g_xTL : g_xTH) + bRowBase + off);
            }
        }
        CP_COMMIT();
    };

    load_stage(0, 0);

    for (int it = 0; it < NCHUNK; it++) {
        const int cur = it & 1;
        CP_WAIT(0);               // stage `it` fully arrived (only group pending)
        __syncthreads();          // publish + everyone done computing stage it-1
        if (it + 1 < NCHUNK) load_stage(it + 1, cur ^ 1);  // overlaps compute

        const uint32_t base = smem_base + (uint32_t)cur * GSTAGE_BYTES;
        const uint32_t AH = base;
        const uint32_t AL = base + GA_BYTES;
        const uint32_t BH = base + 2 * GA_BYTES;
        const uint32_t BL = base + 2 * GA_BYTES + GB_BYTES;

        // ks-loop deliberately NOT unrolled: ~2KB body stays in L0 I$
#pragma unroll 1
        for (int ks = 0; ks < 4; ks++) {
            uint32_t afH[4][4], afL[4][4];
#pragma unroll
            for (int mt = 0; mt < 4; mt++) {
                const int row = m0 + mt * 16 + ((lane >> 3) & 1) * 8 + (lane & 7);
                const int c16 = ks * 2 + (lane >> 4);
                const uint32_t so = SWZ128((uint32_t)(row * 128 + c16 * 16));
                LDSM_X4(afH[mt][0], afH[mt][1], afH[mt][2], afH[mt][3], AH + so);
                LDSM_X4(afL[mt][0], afL[mt][1], afL[mt][2], afL[mt][3], AL + so);
            }
            uint32_t bfH[8][2], bfL[8][2];
#pragma unroll
            for (int j = 0; j < 4; j++) {
                const int row = n0 + j * 16 + (lane >> 4) * 8 + (lane & 7);
                const int c16 = ks * 2 + ((lane >> 3) & 1);
                const uint32_t so = SWZ128((uint32_t)(row * 128 + c16 * 16));
                LDSM_X4(bfH[2 * j][0], bfH[2 * j][1],
                        bfH[2 * j + 1][0], bfH[2 * j + 1][1], BH + so);
                LDSM_X4(bfL[2 * j][0], bfL[2 * j][1],
                        bfL[2 * j + 1][0], bfL[2 * j + 1][1], BL + so);
            }
#pragma unroll
            for (int mt = 0; mt < 4; mt++)
#pragma unroll
                for (int nt = 0; nt < 8; nt++) {
                    MMA16816(acc[mt][nt], afH[mt], bfH[nt]);   // H*H
                    MMA16816(acc[mt][nt], afH[mt], bfL[nt]);   // H*L
                    MMA16816(acc[mt][nt], afL[mt], bfH[nt]);   // L*H
                }
        }
    }

    // Epilogue: thread (g=lane>>2, ti=lane&3) holds (g,2ti),(g,2ti+1),(g+8,..)
    const int g = lane >> 2;
    const int ti = lane & 3;
#pragma unroll
    for (int mt = 0; mt < 4; mt++) {
        const int d0 = tileM + m0 + mt * 16 + g;
        const int d1 = d0 + 8;
        const float bias0 = __ldg(&be[d0]);
        const float bias1 = __ldg(&be[d1]);
        float* y0 = g_y + ((size_t)b * HIGH_DIM + d0) * TDIM + tileN + n0;
        float* y1 = g_y + ((size_t)b * HIGH_DIM + d1) * TDIM + tileN + n0;
#pragma unroll
        for (int nt = 0; nt < 8; nt++) {
            const int col = nt * 8 + 2 * ti;
            float2 v0 = make_float2(acc[mt][nt][0] + bias0, acc[mt][nt][1] + bias0);
            float2 v1 = make_float2(acc[mt][nt][2] + bias1, acc[mt][nt][3] + bias1);
            *reinterpret_cast<float2*>(y0 + col) = v0;
            *reinterpret_cast<float2*>(y1 + col) = v1;
        }
    }
}

// =============================================================================
// Kernel 2: per-row (b,d) top-64 with fp64 boundary arbitration.
// R15 structure + pass-0 histogram FUSED into the global key-load loop
// (eliminates one full smem key scan; selection logic unchanged).
// =============================================================================
__device__ __forceinline__ unsigned f2key(unsigned bits) {
    return bits ^ (((unsigned)((int)bits >> 31)) | 0x80000000u);
}
__device__ __forceinline__ float key2f(unsigned k) {
    unsigned bits = (k & 0x80000000u) ? (k ^ 0x80000000u) : ~k;
    return __uint_as_float(bits);
}

__global__ __launch_bounds__(256) void topk_kernel(
    const float* __restrict__ x,
    const float* __restrict__ We,
    const float* __restrict__ be,
    float* __restrict__ sparse_out)
{
    const int row = blockIdx.x;          // b*HIGH_DIM + d
    const int b = row / HIGH_DIM;
    const int d = row % HIGH_DIM;
    const size_t rowoff = (size_t)row * TDIM;

    __shared__ unsigned keys[TDIM];      // 16 KB
    __shared__ int hist[256];
    __shared__ unsigned s_prefix, s_mask;
    __shared__ int s_need;
    __shared__ int s_above, s_ncand;
    __shared__ int s_cidx[CAND_CAP];
    __shared__ double s_cex[CAND_CAP];
    __shared__ unsigned char s_take[CAND_CAP];

    const int tid = threadIdx.x;
    const int lane = tid & 31;
    const int w = tid >> 5;

    if (tid == 0) { s_prefix = 0u; s_mask = 0u; s_need = KEEP; s_above = 0; s_ncand = 0; }
    hist[tid] = 0;
    __syncthreads();

    // fused: vectorized key load + pass-0 (top byte) histogram
    {
        const uint4* yrow4 = reinterpret_cast<const uint4*>(g_y + rowoff);
        uint4* keys4 = reinterpret_cast<uint4*>(keys);
#pragma unroll
        for (int i = tid; i < TDIM / 4; i += 256) {
            uint4 v = yrow4[i];
            v.x = f2key(v.x); v.y = f2key(v.y); v.z = f2key(v.z); v.w = f2key(v.w);
            keys4[i] = v;
            atomicAdd(&hist[v.x >> 24], 1);
            atomicAdd(&hist[v.y >> 24], 1);
            atomicAdd(&hist[v.z >> 24], 1);
            atomicAdd(&hist[v.w >> 24], 1);
        }
    }
    __syncthreads();

    // selection helper runs for pass 0 now, then passes 1..3 with smem scans
    for (int pass = 0; pass < 4; pass++) {
        const int shift = 24 - pass * 8;
        if (pass > 0) {
            hist[tid] = 0;
            __syncthreads();
            const unsigned pf = s_prefix, mk = s_mask;
            const uint4* keys4 = reinterpret_cast<const uint4*>(keys);
#pragma unroll
            for (int i = tid; i < TDIM / 4; i += 256) {
                uint4 k = keys4[i];
                if ((k.x & mk) == pf) atomicAdd(&hist[(k.x >> shift) & 0xFF], 1);
                if ((k.y & mk) == pf) atomicAdd(&hist[(k.y >> shift) & 0xFF], 1);
                if ((k.z & mk) == pf) atomicAdd(&hist[(k.z >> shift) & 0xFF], 1);
                if ((k.w & mk) == pf) atomicAdd(&hist[(k.w >> shift) & 0xFF], 1);
            }
            __syncthreads();
        }
        // warp-parallel bin selection (warp 0): lane owns bins [8l, 8l+7]
        if (w == 0) {
            const int need = s_need;
            int h[8];
            int local = 0;
#pragma unroll
            for (int i = 0; i < 8; i++) { h[i] = hist[lane * 8 + i]; local += h[i]; }
            int T = local;
#pragma unroll
            for (int o = 1; o < 32; o <<= 1) {
                int v = __shfl_down_sync(0xFFFFFFFFu, T, o);
                if (lane + o < 32) T += v;
            }
            int tnext = __shfl_down_sync(0xFFFFFFFFu, T, 1);
            if (lane == 31) tnext = 0;
            if (T >= need && tnext < need) {
                int cum = tnext;
                int bin = 0;
#pragma unroll
                for (int i = 7; i >= 0; i--) {
                    if (cum + h[i] >= need) { bin = lane * 8 + i; break; }
                    cum += h[i];
                }
                s_need = need - cum;
                s_prefix = s_prefix | ((unsigned)bin << shift);
                s_mask = s_mask | (0xFFu << shift);
            }
        }
        __syncthreads();
    }

    const float v64 = key2f(s_prefix);
    const float hi = v64 + TAU;
    const float lo = v64 - TAU;
    const unsigned khi = f2key(__float_as_uint(hi));
    const unsigned klo = f2key(__float_as_uint(lo));

    // classify on keys directly (order-preserving): k > khi above; k >= klo in band
    {
        const uint4* keys4 = reinterpret_cast<const uint4*>(keys);
#pragma unroll
        for (int i = tid; i < TDIM / 4; i += 256) {
            uint4 k = keys4[i];
            int above = (k.x > khi) + (k.y > khi) + (k.z > khi) + (k.w > khi);
            if (above) atomicAdd(&s_above, above);
#pragma unroll
            for (int e = 0; e < 4; e++) {
                unsigned ke = (e == 0) ? k.x : (e == 1) ? k.y : (e == 2) ? k.z : k.w;
                if (ke <= khi && ke >= klo) {
                    int p = atomicAdd(&s_ncand, 1);
                    if (p < CAND_CAP) s_cidx[p] = i * 4 + e;
                }
            }
        }
    }
    __syncthreads();

    const int slots = KEEP - s_above;
    const int nc = min(s_ncand, CAND_CAP);
    const bool simple = (s_ncand == slots);

    if (!simple) {
        const float* wr = We + (size_t)d * MODEL_DIM;
        const float* xb = x + (size_t)b * MODEL_DIM * TDIM;
        for (int p = w; p < nc; p += 8) {
            const int t = s_cidx[p];
            double s = 0.0;
            for (int c = lane; c < MODEL_DIM; c += 32)
                s += (double)wr[c] * (double)xb[(size_t)c * TDIM + t];
#pragma unroll
            for (int o = 16; o > 0; o >>= 1)
                s += __shfl_down_sync(0xFFFFFFFFu, s, o);
            if (lane == 0) s_cex[p] = s + (double)be[d];
        }
        __syncthreads();
        for (int p = tid; p < nc; p += 256) {
            const float ef = (float)s_cex[p];
            const int gi = s_cidx[p];
            int better = 0;
            for (int q = 0; q < nc; q++) {
                if (q == p) continue;
                const float qf = (float)s_cex[q];
                if (qf > ef || (qf == ef && s_cidx[q] < gi)) better++;
            }
            s_take[p] = (better < slots) ? 1 : 0;
        }
        __syncthreads();
    }

    // vectorized writeback + bucket append
    {
        float4* sp4 = reinterpret_cast<float4*>(sparse_out + rowoff);
        const uint4* keys4 = reinterpret_cast<const uint4*>(keys);
#pragma unroll
        for (int i = tid; i < TDIM / 4; i += 256) {
            uint4 k = keys4[i];
            float4 outv;
#pragma unroll
            for (int e = 0; e < 4; e++) {
                unsigned ke = (e == 0) ? k.x : (e == 1) ? k.y : (e == 2) ? k.z : k.w;
                bool take;
                if (ke > khi) take = true;
                else if (ke < klo) take = false;
                else if (simple) take = true;
                else {
                    take = false;
                    const int gi = i * 4 + e;
                    for (int p = 0; p < nc; p++)
                        if (s_cidx[p] == gi) { take = (s_take[p] != 0); break; }
                }
                float yv = take ? key2f(ke) : 0.f;
                if (e == 0) outv.x = yv; else if (e == 1) outv.y = yv;
                else if (e == 2) outv.z = yv; else outv.w = yv;
                if (take) {
                    const int col = b * TDIM + i * 4 + e;
                    int pos = atomicAdd(&g_colcnt[col], 1);
                    if (pos < COLCAP) {
                        g_cold[(size_t)col * COLCAP + pos] = (short)d;
                        g_colv[(size_t)col * COLCAP + pos] = key2f(ke);
                    }
                }
            }
            sp4[i] = outv;
        }
    }
}

// =============================================================================
// Kernel 3: transpose W_c [1024 x 2048] -> W_cT [2048 x 1024]
// =============================================================================
__global__ void transpose_wc_kernel(const float* __restrict__ Wc)
{
    __shared__ float tile[32][33];
    const int d0 = blockIdx.x * 32;
    const int m0 = blockIdx.y * 32;
    const int tx = threadIdx.x, ty = threadIdx.y;
    for (int i = ty; i < 32; i += 8)
        tile[i][tx] = Wc[(size_t)(m0 + i) * HIGH_DIM + d0 + tx];
    __syncthreads();
    for (int i = ty; i < 32; i += 8)
        g_WcT[(size_t)(d0 + i) * MODEL_DIM + m0 + tx] = tile[tx][i];
}

// =============================================================================
// Kernel 4: sparse contract from compact per-column lists, coalesced epilogue.
// (Measured near its ~4GB L2-read floor; unchanged.)
// =============================================================================
#define TTILE 8

__global__ __launch_bounds__(256) void contract_kernel(
    const float* __restrict__ bc,
    float* __restrict__ out)
{
    const int b = blockIdx.y;
    const int t0 = blockIdx.x * TTILE;

    __shared__ short sd[TTILE][COLCAP];
    __shared__ float sv[TTILE][COLCAP];
    __shared__ int scnt[TTILE];
    __shared__ float sm_out[TTILE][MODEL_DIM];   // 32 KB

    const int tid = threadIdx.x;
    const int lane = tid & 31;
    const int w = tid >> 5;             // 8 warps = 8 columns

    // load this warp's column list
    {
        const int col = b * TDIM + t0 + w;
        const int n = min(g_colcnt[col], COLCAP);
        if (lane == 0) scnt[w] = n;
        const size_t base = (size_t)col * COLCAP;
        for (int j = lane; j < n; j += 32) {
            sd[w][j] = g_cold[base + j];
            sv[w][j] = g_colv[base + j];
        }
    }
    __syncwarp();

    // sort by d ascending (deterministic order); n ~ 32, lane 0 insertion sort
    if (lane == 0) {
        const int n = scnt[w];
        for (int i = 1; i < n; i++) {
            short dk = sd[w][i]; float vk = sv[w][i];
            int j = i - 1;
            while (j >= 0 && sd[w][j] > dk) {
                sd[w][j + 1] = sd[w][j]; sv[w][j + 1] = sv[w][j]; j--;
            }
            sd[w][j + 1] = dk; sv[w][j + 1] = vk;
        }
    }
    __syncwarp();

    // accumulate: lane covers m = i*128 + lane*4 .. +3
    {
        const int n = scnt[w];
        float4 a4[8];
#pragma unroll
        for (int i = 0; i < 8; i++) a4[i] = make_float4(0.f, 0.f, 0.f, 0.f);
        for (int j = 0; j < n; j++) {
            const float val = sv[w][j];
            const float4* wr4 = reinterpret_cast<const float4*>(
                g_WcT + (size_t)sd[w][j] * MODEL_DIM);
#pragma unroll
            for (int i = 0; i < 8; i++) {
                float4 v = wr4[i * 32 + lane];
                a4[i].x = fmaf(val, v.x, a4[i].x);
                a4[i].y = fmaf(val, v.y, a4[i].y);
                a4[i].z = fmaf(val, v.z, a4[i].z);
                a4[i].w = fmaf(val, v.w, a4[i].w);
            }
        }
#pragma unroll
        for (int i = 0; i < 8; i++)
            *reinterpret_cast<float4*>(&sm_out[w][i * 128 + lane * 4]) = a4[i];
    }
    __syncthreads();

    // coalesced writeback: thread handles rows m = tid + 256*r
    float* ob = out + (size_t)b * MODEL_DIM * TDIM + t0;
#pragma unroll
    for (int r = 0; r < 4; r++) {
        const int m = tid + 256 * r;
        const float bias = bc[m];
        float4 v0, v1;
        v0.x = sm_out[0][m] + bias; v0.y = sm_out[1][m] + bias;
        v0.z = sm_out[2][m] + bias; v0.w = sm_out[3][m] + bias;
        v1.x = sm_out[4][m] + bias; v1.y = sm_out[5][m] + bias;
        v1.z = sm_out[6][m] + bias; v1.w = sm_out[7][m] + bias;
        float* op = ob + (size_t)m * TDIM;
        *reinterpret_cast<float4*>(op) = v0;
        *reinterpret_cast<float4*>(op + 4) = v1;
    }
}

// =============================================================================
// launch
// =============================================================================
extern "C" void kernel_launch(void* const* d_in, const int* in_sizes, int n_in,
                              void* d_out, int out_size)
{
    const float* x  = (const float*)d_in[0];   // [8,1024,4096]
    const float* We = (const float*)d_in[1];   // [2048,1024]
    const float* be = (const float*)d_in[2];   // [2048]
    const float* Wc = (const float*)d_in[3];   // [1024,2048]
    const float* bc = (const float*)d_in[4];   // [1024]

    float* out_ptr = (float*)d_out;                                       // [8,1024,4096]
    float* sparse_ptr = (float*)d_out + (size_t)BATCH * MODEL_DIM * TDIM; // [8,2048,4096]

    cudaFuncSetAttribute(gemm_expand_mma,
                         cudaFuncAttributeMaxDynamicSharedMemorySize, GSMEM_TOTAL);

    // prep: bf16 splits (+fused bucket reset) + W_c transpose
    split_we_kernel<<<(HIGH_DIM * MODEL_DIM) / 256, 256>>>(We);
    split_x_kernel<<<dim3(TDIM / 32, MODEL_DIM / 32, BATCH), dim3(32, 8)>>>(x);
    transpose_wc_kernel<<<dim3(HIGH_DIM / 32, MODEL_DIM / 32), dim3(32, 8)>>>(Wc);

    // expand GEMM on tensor cores (HMMA, 128x256 tile, BK=64 double buffer)
    gemm_expand_mma<<<dim3(TDIM / 256, HIGH_DIM / 128, BATCH), 256, GSMEM_TOTAL>>>(be);

    // top-k (writes sparse region + column buckets)
    topk_kernel<<<BATCH * HIGH_DIM, 256>>>(x, We, be, sparse_ptr);

    // contract from compact lists
    contract_kernel<<<dim3(TDIM / TTILE, BATCH), 256>>>(bc, out_ptr);
}